// round 4
// baseline (speedup 1.0000x reference)
#include <cuda_runtime.h>
#include <cstdint>

#define S_   24
#define B_   256
#define D_   1024
#define H_   16
#define DH_  64
#define L_   12
#define V_   32000
#define NTOK (S_ * B_)   // 6144

// Scratch (allocation-free rule: __device__ globals)
__device__ float g_x[NTOK * D_];
__device__ float g_q[NTOK * D_];
__device__ float g_k[NTOK * D_];
__device__ float g_v[NTOK * D_];

// ---------------------------------------------------------------------------
// Helpers
// ---------------------------------------------------------------------------
__device__ __forceinline__ uint32_t smem_u32(const void* p) {
    uint32_t a;
    asm("{ .reg .u64 t; cvta.to.shared.u64 t, %1; cvt.u32.u64 %0, t; }" : "=r"(a) : "l"(p));
    return a;
}
__device__ __forceinline__ uint32_t f2tf(float x) {
    uint32_t y;
    asm("cvt.rna.tf32.f32 %0, %1;" : "=r"(y) : "f"(x));
    return y;
}
__device__ __forceinline__ void mma_tf32(float* d, const uint32_t* a, const uint32_t* b) {
    asm volatile(
        "mma.sync.aligned.m16n8k8.row.col.f32.tf32.tf32.f32 "
        "{%0,%1,%2,%3}, {%4,%5,%6,%7}, {%8,%9}, {%0,%1,%2,%3};"
        : "+f"(d[0]), "+f"(d[1]), "+f"(d[2]), "+f"(d[3])
        : "r"(a[0]), "r"(a[1]), "r"(a[2]), "r"(a[3]), "r"(b[0]), "r"(b[1]));
}
#define LDS128(a,b,c,d,addr) asm volatile("ld.shared.v4.b32 {%0,%1,%2,%3}, [%4];" \
    : "=r"(a),"=r"(b),"=r"(c),"=r"(d) : "r"(addr))
#define LDS64(a,b,addr) asm volatile("ld.shared.v2.b32 {%0,%1}, [%2];" \
    : "=r"(a),"=r"(b) : "r"(addr))
#define STS32(addr,v) asm volatile("st.shared.b32 [%0], %1;" :: "r"(addr), "r"(v) : "memory")

// ---------------------------------------------------------------------------
// Embedding
// ---------------------------------------------------------------------------
__global__ void __launch_bounds__(256) embed_kernel(
    const int* __restrict__ inp,
    const float* __restrict__ tok,
    const float* __restrict__ pe)
{
    int e4 = blockIdx.x * 256 + threadIdx.x;
    int e  = e4 * 4;
    int n  = e / D_;
    int d  = e % D_;
    int s  = n / B_;
    int t  = inp[n];
    float4 a = *(const float4*)(tok + (size_t)t * D_ + d);
    float4 p = *(const float4*)(pe + (size_t)s * D_ + d);
    a.x += p.x; a.y += p.y; a.z += p.z; a.w += p.w;
    *(float4*)(g_x + e) = a;
}

// ---------------------------------------------------------------------------
// TF32 mma GEMM, fragment-major smem layout.
// C[m,n] = sum_k A[m,k]*B[n,k] + bias[n]
// Block tile 128x256, BK=16, double-buffered. 8 warps, warp tile 64x64.
//
// Fragment layout (floats):
//  A: m = wm*64 + i*16 + p*8 + g ; k = ks*8 + kh*4 + t
//     idxA = (((wm*2+ks)*4 + i)*8 + g)*16 + (t ^ xg)*4 + kh*2 + p,  xg=(g&3)^(g>>2)
//     -> consumer LDS.128 yields {a0,a1,a2,a3} for mma directly.
//  B: n = wn*64 + j*8 + g ; k same
//     idxB = ((((wn*2+ks)*8 + j)*8 + g)*4 + (t ^ xg ^ ((j&1)<<1)))*2 + kh
//     -> consumer LDS.64 yields {b0,b1}.
// ---------------------------------------------------------------------------
#define BK_ 16
#define KT  (D_ / BK_)   // 64

__device__ __forceinline__ void gemm_body(
    const float* __restrict__ A, const float* __restrict__ Bw,
    const float* __restrict__ bias, float* __restrict__ C,
    int N, int bm, int bn)
{
    __shared__ uint32_t As[2][2048];   //  8KB per buffer
    __shared__ uint32_t Bs[2][4096];   // 16KB per buffer

    const int tid  = threadIdx.x;
    const int lane = tid & 31;
    const int wid  = tid >> 5;
    const int grp  = lane >> 2;
    const int tig  = lane & 3;
    const int wm   = wid >> 2;        // 0..1
    const int wn   = wid & 3;         // 0..3
    const int xc   = (grp & 3) ^ (grp >> 2);

    const uint32_t asB = smem_u32(As);
    const uint32_t bsB = smem_u32(Bs);

    // ---- producer mapping ----
    // A: thread -> row pr = tid>>1, k-half pks = tid&1 (8 floats)
    const int pr  = tid >> 1;
    const int pks = tid & 1;
    const int pg  = pr & 7;
    const int pp  = (pr >> 3) & 1;
    const int pi  = (pr >> 4) & 3;
    const int pwm = pr >> 6;
    const int xA  = (pg & 3) ^ (pg >> 2);
    const uint32_t aQ = ((uint32_t)(((pwm * 2 + pks) * 4 + pi) * 8 + pg)) * 64u + pp * 4u; // bytes
    // B: thread -> row n = tid (16 floats)
    const int nn  = tid;
    const int ng  = nn & 7;
    const int nj  = (nn >> 3) & 7;
    const int nw  = nn >> 6;
    const int xB  = (ng & 3) ^ (ng >> 2) ^ ((nj & 1) << 1);
    const uint32_t bR0 = ((uint32_t)(((nw * 2 + 0) * 8 + nj) * 8 + ng)) * 32u;  // bytes, ks=0
    const uint32_t bR1 = ((uint32_t)(((nw * 2 + 1) * 8 + nj) * 8 + ng)) * 32u;  // bytes, ks=1

    const float* Ag = A  + (size_t)(bm + pr) * D_ + pks * 8;
    const float* Bg = Bw + (size_t)(bn + nn) * D_;

    float acc[4][8][4];
    #pragma unroll
    for (int i = 0; i < 4; i++)
        #pragma unroll
        for (int j = 0; j < 8; j++)
            #pragma unroll
            for (int c = 0; c < 4; c++) acc[i][j][c] = 0.f;

    float4 va0, va1, vb0, vb1, vb2, vb3;

    // ---- prologue: tile 0 ----
    va0 = *(const float4*)(Ag);      va1 = *(const float4*)(Ag + 4);
    vb0 = *(const float4*)(Bg);      vb1 = *(const float4*)(Bg + 4);
    vb2 = *(const float4*)(Bg + 8);  vb3 = *(const float4*)(Bg + 12);

    #define STS_TILE(buf) do {                                                  \
        const uint32_t ab = asB + (buf) * 8192u;                                \
        const uint32_t bb = bsB + (buf) * 16384u;                               \
        const float* f;                                                          \
        f = (const float*)&va0;                                                  \
        _Pragma("unroll") for (int t = 0; t < 4; t++)                            \
            STS32(ab + aQ + ((t ^ xA) << 4) + 0u, f2tf(f[t]));                  \
        f = (const float*)&va1;                                                  \
        _Pragma("unroll") for (int t = 0; t < 4; t++)                            \
            STS32(ab + aQ + ((t ^ xA) << 4) + 8u, f2tf(f[t]));                  \
        f = (const float*)&vb0;                                                  \
        _Pragma("unroll") for (int t = 0; t < 4; t++)                            \
            STS32(bb + bR0 + ((t ^ xB) << 3) + 0u, f2tf(f[t]));                 \
        f = (const float*)&vb1;                                                  \
        _Pragma("unroll") for (int t = 0; t < 4; t++)                            \
            STS32(bb + bR0 + ((t ^ xB) << 3) + 4u, f2tf(f[t]));                 \
        f = (const float*)&vb2;                                                  \
        _Pragma("unroll") for (int t = 0; t < 4; t++)                            \
            STS32(bb + bR1 + ((t ^ xB) << 3) + 0u, f2tf(f[t]));                 \
        f = (const float*)&vb3;                                                  \
        _Pragma("unroll") for (int t = 0; t < 4; t++)                            \
            STS32(bb + bR1 + ((t ^ xB) << 3) + 4u, f2tf(f[t]));                 \
    } while (0)

    STS_TILE(0);
    __syncthreads();

    int cur = 0;
    for (int t = 0; t < KT; t++) {
        if (t + 1 < KT) {
            const float* Ag2 = Ag + (t + 1) * BK_;
            const float* Bg2 = Bg + (t + 1) * BK_;
            va0 = *(const float4*)(Ag2);      va1 = *(const float4*)(Ag2 + 4);
            vb0 = *(const float4*)(Bg2);      vb1 = *(const float4*)(Bg2 + 4);
            vb2 = *(const float4*)(Bg2 + 8);  vb3 = *(const float4*)(Bg2 + 12);
        }

        // ---- compute from buffer cur ----
        {
            const uint32_t ab = asB + cur * 8192u;
            const uint32_t bb = bsB + cur * 16384u;
            #pragma unroll
            for (int ks = 0; ks < 2; ks++) {
                uint32_t af[4][4];
                #pragma unroll
                for (int i = 0; i < 4; i++) {
                    uint32_t ad = ab + (uint32_t)(((wm * 2 + ks) * 4 + i) * 512)
                                + grp * 64u + ((tig ^ xc) << 4);
                    LDS128(af[i][0], af[i][1], af[i][2], af[i][3], ad);
                }
                uint32_t bf[8][2];
                #pragma unroll
                for (int j = 0; j < 8; j++) {
                    uint32_t bd = bb + (uint32_t)(((wn * 2 + ks) * 8 + j) * 256)
                                + grp * 32u + ((tig ^ xc ^ ((j & 1) << 1)) << 3);
                    LDS64(bf[j][0], bf[j][1], bd);
                }
                #pragma unroll
                for (int i = 0; i < 4; i++)
                    #pragma unroll
                    for (int j = 0; j < 8; j++)
                        mma_tf32(acc[i][j], af[i], bf[j]);
            }
        }

        if (t + 1 < KT) STS_TILE(cur ^ 1);
        __syncthreads();
        cur ^= 1;
    }

    // ---- epilogue ----
    #pragma unroll
    for (int i = 0; i < 4; i++) {
        const int r0 = bm + wm * 64 + i * 16 + grp;
        #pragma unroll
        for (int j = 0; j < 8; j++) {
            const int col = bn + wn * 64 + j * 8 + tig * 2;
            float2 bv = *(const float2*)(bias + col);
            float2 v0 = { acc[i][j][0] + bv.x, acc[i][j][1] + bv.y };
            float2 v1 = { acc[i][j][2] + bv.x, acc[i][j][3] + bv.y };
            *(float2*)(C + (size_t)r0 * N + col)       = v0;
            *(float2*)(C + (size_t)(r0 + 8) * N + col) = v1;
        }
    }
}

__global__ void __launch_bounds__(256, 1) qkv_gemm_kernel(
    const float* __restrict__ qw, const float* __restrict__ qb,
    const float* __restrict__ kw, const float* __restrict__ kb,
    const float* __restrict__ vw, const float* __restrict__ vb)
{
    const float* W; const float* bb; float* C;
    if (blockIdx.z == 0)      { W = qw; bb = qb; C = g_q; }
    else if (blockIdx.z == 1) { W = kw; bb = kb; C = g_k; }
    else                      { W = vw; bb = vb; C = g_v; }
    gemm_body(g_x, W, bb, C, D_, blockIdx.x * 128, blockIdx.y * 256);
}

__global__ void __launch_bounds__(256, 1) out_gemm_kernel(
    const float* __restrict__ W, const float* __restrict__ bias,
    float* __restrict__ C)
{
    gemm_body(g_x, W, bias, C, V_, blockIdx.x * 128, blockIdx.y * 256);
}

// ---------------------------------------------------------------------------
// Attention: one block per (b, h). S=24, DH=64. Fused residual. float4 I/O.
// ---------------------------------------------------------------------------
__global__ void __launch_bounds__(256) attn_kernel()
{
    __shared__ float qs[S_][DH_];
    __shared__ float ks_[S_][DH_];
    __shared__ float vs[S_][DH_];
    __shared__ float sc[S_][S_];

    const int bh  = blockIdx.x;
    const int b   = bh >> 4;
    const int h   = bh & 15;
    const int tid = threadIdx.x;

    // 384 float4 per matrix
    for (int idx = tid; idx < S_ * DH_ / 4; idx += 256) {
        int s = idx >> 4, c4 = (idx & 15) * 4;
        size_t off = ((size_t)s * B_ + b) * D_ + h * DH_ + c4;
        *(float4*)&qs[s][c4]  = *(const float4*)(g_q + off);
        *(float4*)&ks_[s][c4] = *(const float4*)(g_k + off);
        *(float4*)&vs[s][c4]  = *(const float4*)(g_v + off);
    }
    __syncthreads();

    const float scale = 0.03125f;   // 1/sqrt(1024)
    for (int idx = tid; idx < S_ * S_; idx += 256) {
        int s = idx / S_, t = idx % S_;
        float dot = 0.f;
        #pragma unroll
        for (int d = 0; d < DH_; d++) dot = fmaf(qs[s][d], ks_[t][d], dot);
        sc[s][t] = dot * scale;
    }
    __syncthreads();

    if (tid < S_) {
        float m = -1e30f;
        #pragma unroll
        for (int t = 0; t < S_; t++) m = fmaxf(m, sc[tid][t]);
        float sum = 0.f;
        #pragma unroll
        for (int t = 0; t < S_; t++) {
            float e = expf(sc[tid][t] - m);
            sc[tid][t] = e;
            sum += e;
        }
        float inv = 1.f / sum;
        #pragma unroll
        for (int t = 0; t < S_; t++) sc[tid][t] *= inv;
    }
    __syncthreads();

    for (int idx = tid; idx < S_ * DH_ / 4; idx += 256) {
        int s = idx >> 4, c4 = (idx & 15) * 4;
        float4 o = {0.f, 0.f, 0.f, 0.f};
        #pragma unroll
        for (int t = 0; t < S_; t++) {
            float p = sc[s][t];
            float4 vv = *(const float4*)&vs[t][c4];
            o.x = fmaf(p, vv.x, o.x);
            o.y = fmaf(p, vv.y, o.y);
            o.z = fmaf(p, vv.z, o.z);
            o.w = fmaf(p, vv.w, o.w);
        }
        size_t off = ((size_t)s * B_ + b) * D_ + h * DH_ + c4;
        float4 xv = *(const float4*)(g_x + off);
        xv.x += o.x; xv.y += o.y; xv.z += o.z; xv.w += o.w;
        *(float4*)(g_x + off) = xv;
    }
}

// ---------------------------------------------------------------------------
// Launch
// ---------------------------------------------------------------------------
extern "C" void kernel_launch(void* const* d_in, const int* in_sizes, int n_in,
                              void* d_out, int out_size)
{
    const int*   inp = (const int*)  d_in[0];
    const float* tok = (const float*)d_in[2];
    const float* pe  = (const float*)d_in[3];
    const float* qw  = (const float*)d_in[4];
    const float* qb  = (const float*)d_in[5];
    const float* kw  = (const float*)d_in[6];
    const float* kb  = (const float*)d_in[7];
    const float* vw  = (const float*)d_in[8];
    const float* vb  = (const float*)d_in[9];
    const float* ow  = (const float*)d_in[10];
    const float* ob  = (const float*)d_in[11];
    float* out = (float*)d_out;

    embed_kernel<<<NTOK * D_ / 4 / 256, 256>>>(inp, tok, pe);

    for (int l = 0; l < L_; l++) {
        const size_t wo = (size_t)l * D_ * D_;
        const size_t bo = (size_t)l * D_;
        qkv_gemm_kernel<<<dim3(NTOK / 128, D_ / 256, 3), 256>>>(
            qw + wo, qb + bo, kw + wo, kb + bo, vw + wo, vb + bo);
        attn_kernel<<<B_ * H_, 256>>>();
    }

    out_gemm_kernel<<<dim3(NTOK / 128, V_ / 256), 256>>>(ow, ob, out);
}

// round 5
// speedup vs baseline: 1.0174x; 1.0174x over previous
#include <cuda_runtime.h>
#include <cstdint>

#define S_   24
#define B_   256
#define D_   1024
#define H_   16
#define DH_  64
#define L_   12
#define V_   32000
#define NTOK (S_ * B_)   // 6144

// Scratch (allocation-free rule: __device__ globals)
__device__ float g_x[NTOK * D_];
__device__ float g_q[NTOK * D_];
__device__ float g_k[NTOK * D_];
__device__ float g_v[NTOK * D_];

// ---------------------------------------------------------------------------
// Helpers
// ---------------------------------------------------------------------------
__device__ __forceinline__ uint32_t smem_u32(const void* p) {
    uint32_t a;
    asm("{ .reg .u64 t; cvta.to.shared.u64 t, %1; cvt.u32.u64 %0, t; }" : "=r"(a) : "l"(p));
    return a;
}
__device__ __forceinline__ uint32_t f2tf(float x) {
    uint32_t y;
    asm("cvt.rna.tf32.f32 %0, %1;" : "=r"(y) : "f"(x));
    return y;
}
__device__ __forceinline__ float ldsf(uint32_t a) {
    float v;
    asm volatile("ld.shared.f32 %0, [%1];" : "=f"(v) : "r"(a));
    return v;
}
__device__ __forceinline__ void mma_tf32(float* d, const uint32_t* a, const uint32_t* b) {
    asm volatile(
        "mma.sync.aligned.m16n8k8.row.col.f32.tf32.tf32.f32 "
        "{%0,%1,%2,%3}, {%4,%5,%6,%7}, {%8,%9}, {%0,%1,%2,%3};"
        : "+f"(d[0]), "+f"(d[1]), "+f"(d[2]), "+f"(d[3])
        : "r"(a[0]), "r"(a[1]), "r"(a[2]), "r"(a[3]), "r"(b[0]), "r"(b[1]));
}
#define CPA16(dst, src) asm volatile("cp.async.ca.shared.global [%0], [%1], 16;" \
    :: "r"(dst), "l"(src) : "memory")
#define CPA_COMMIT() asm volatile("cp.async.commit_group;" ::: "memory")
#define CPA_WAIT2()  asm volatile("cp.async.wait_group 2;" ::: "memory")

// ---------------------------------------------------------------------------
// Embedding
// ---------------------------------------------------------------------------
__global__ void __launch_bounds__(256) embed_kernel(
    const int* __restrict__ inp,
    const float* __restrict__ tok,
    const float* __restrict__ pe)
{
    int e4 = blockIdx.x * 256 + threadIdx.x;
    int e  = e4 * 4;
    int n  = e / D_;
    int d  = e % D_;
    int s  = n / B_;
    int t  = inp[n];
    float4 a = *(const float4*)(tok + (size_t)t * D_ + d);
    float4 p = *(const float4*)(pe + (size_t)s * D_ + d);
    a.x += p.x; a.y += p.y; a.z += p.z; a.w += p.w;
    *(float4*)(g_x + e) = a;
}

// ---------------------------------------------------------------------------
// TF32 mma GEMM with cp.async 4-stage pipeline.
// C[m,n] = sum_k A[m,k]*B[n,k] + bias[n]
// Block tile 128x256, BK=16. 8 warps, warp tile 64x64.
// SMEM per stage: A 8KB (128 rows x 64B) + B 16KB (256 rows x 64B) = 24KB.
// Row layout: 16 fp32 (4 x 16B chunks); chunk c stored at (c ^ ((row>>1)&3)).
//   -> every fragment scalar-LDS (8 rows x 4 k across 32 lanes) is conflict-free.
// Consumer converts with cvt.rna.tf32 after LDS (numerics match prior rounds).
// ---------------------------------------------------------------------------
#define BK_    16
#define KT     (D_ / BK_)   // 64
#define STAGEB 24576u       // bytes per stage
#define SMEM_BYTES (4 * 24576)

__device__ __forceinline__ void gemm_body(
    const float* __restrict__ A, const float* __restrict__ Bw,
    const float* __restrict__ bias, float* __restrict__ C,
    int N, int bm, int bn)
{
    extern __shared__ char smem[];
    const uint32_t sbase = smem_u32(smem);

    const int tid  = threadIdx.x;
    const int lane = tid & 31;
    const int wid  = tid >> 5;
    const int grp  = lane >> 2;      // 0..7
    const int tig  = lane & 3;       // 0..3
    const int wm   = wid >> 2;       // 0..1
    const int wn   = wid & 3;        // 0..3

    // ---- producer mapping ----
    // A: thread -> row pm = tid>>1, chunk pair pu = (tid&1)*2
    const int pm = tid >> 1;
    const int pu = (tid & 1) * 2;
    const uint32_t xa = (uint32_t)((pm >> 1) & 3);
    const uint32_t aoff0 = (uint32_t)pm * 64u + ((((uint32_t)pu    ) ^ xa) << 4);
    const uint32_t aoff1 = (uint32_t)pm * 64u + ((((uint32_t)pu + 1) ^ xa) << 4);
    const float* agp = A + (size_t)(bm + pm) * D_ + pu * 4;
    // B: thread -> row pn = tid, all 4 chunks
    const int pn = tid;
    const uint32_t xb = (uint32_t)((pn >> 1) & 3);
    uint32_t boff[4];
    #pragma unroll
    for (int c = 0; c < 4; c++)
        boff[c] = (uint32_t)pn * 64u + (((uint32_t)c ^ xb) << 4);
    const float* bgp = Bw + (size_t)(bn + pn) * D_;

    #define ISSUE(t) do {                                                      \
        const uint32_t stb = sbase + (uint32_t)((t) & 3) * STAGEB;             \
        const float* a0 = agp + (t) * BK_;                                     \
        CPA16(stb + aoff0, a0);                                                \
        CPA16(stb + aoff1, a0 + 4);                                            \
        const float* b0 = bgp + (t) * BK_;                                     \
        CPA16(stb + 8192u + boff[0], b0);                                      \
        CPA16(stb + 8192u + boff[1], b0 + 4);                                  \
        CPA16(stb + 8192u + boff[2], b0 + 8);                                  \
        CPA16(stb + 8192u + boff[3], b0 + 12);                                 \
    } while (0)

    float acc[4][8][4];
    #pragma unroll
    for (int i = 0; i < 4; i++)
        #pragma unroll
        for (int j = 0; j < 8; j++)
            #pragma unroll
            for (int c = 0; c < 4; c++) acc[i][j][c] = 0.f;

    // prologue: stages 0..2
    ISSUE(0); CPA_COMMIT();
    ISSUE(1); CPA_COMMIT();
    ISSUE(2); CPA_COMMIT();

    // precompute consumer bases
    uint32_t abase[4][2];   // [i][p] -> row byte base + tig*4
    uint32_t axor[4][2];
    #pragma unroll
    for (int i = 0; i < 4; i++) {
        int m0 = wm * 64 + i * 16 + grp;
        int m1 = m0 + 8;
        abase[i][0] = (uint32_t)m0 * 64u + (uint32_t)tig * 4u;
        abase[i][1] = (uint32_t)m1 * 64u + (uint32_t)tig * 4u;
        axor[i][0]  = (uint32_t)((m0 >> 1) & 3);
        axor[i][1]  = (uint32_t)((m1 >> 1) & 3);
    }
    uint32_t bbase[8], bxor[8];
    #pragma unroll
    for (int j = 0; j < 8; j++) {
        int n0 = wn * 64 + j * 8 + grp;
        bbase[j] = (uint32_t)n0 * 64u + (uint32_t)tig * 4u;
        bxor[j]  = (uint32_t)((n0 >> 1) & 3);
    }

    for (int t = 0; t < KT; t++) {
        CPA_WAIT2();
        __syncthreads();

        const uint32_t ab = sbase + (uint32_t)(t & 3) * STAGEB;
        const uint32_t bb = ab + 8192u;

        #pragma unroll
        for (int ks = 0; ks < 2; ks++) {
            const uint32_t c0 = (uint32_t)(ks * 2);
            uint32_t af[4][4];
            #pragma unroll
            for (int i = 0; i < 4; i++) {
                af[i][0] = f2tf(ldsf(ab + abase[i][0] + (((c0    ) ^ axor[i][0]) << 4)));
                af[i][1] = f2tf(ldsf(ab + abase[i][1] + (((c0    ) ^ axor[i][1]) << 4)));
                af[i][2] = f2tf(ldsf(ab + abase[i][0] + (((c0 + 1) ^ axor[i][0]) << 4)));
                af[i][3] = f2tf(ldsf(ab + abase[i][1] + (((c0 + 1) ^ axor[i][1]) << 4)));
            }
            uint32_t bf[8][2];
            #pragma unroll
            for (int j = 0; j < 8; j++) {
                bf[j][0] = f2tf(ldsf(bb + bbase[j] + (((c0    ) ^ bxor[j]) << 4)));
                bf[j][1] = f2tf(ldsf(bb + bbase[j] + (((c0 + 1) ^ bxor[j]) << 4)));
            }
            #pragma unroll
            for (int i = 0; i < 4; i++)
                #pragma unroll
                for (int j = 0; j < 8; j++)
                    mma_tf32(acc[i][j], af[i], bf[j]);
        }

        if (t + 3 < KT) ISSUE(t + 3);
        CPA_COMMIT();   // empty group when nothing issued keeps wait-count math exact
    }

    // ---- epilogue ----
    #pragma unroll
    for (int i = 0; i < 4; i++) {
        const int r0 = bm + wm * 64 + i * 16 + grp;
        #pragma unroll
        for (int j = 0; j < 8; j++) {
            const int col = bn + wn * 64 + j * 8 + tig * 2;
            float2 bv = *(const float2*)(bias + col);
            float2 v0 = { acc[i][j][0] + bv.x, acc[i][j][1] + bv.y };
            float2 v1 = { acc[i][j][2] + bv.x, acc[i][j][3] + bv.y };
            *(float2*)(C + (size_t)r0 * N + col)       = v0;
            *(float2*)(C + (size_t)(r0 + 8) * N + col) = v1;
        }
    }
    #undef ISSUE
}

__global__ void __launch_bounds__(256, 1) qkv_gemm_kernel(
    const float* __restrict__ qw, const float* __restrict__ qb,
    const float* __restrict__ kw, const float* __restrict__ kb,
    const float* __restrict__ vw, const float* __restrict__ vb)
{
    const float* W; const float* bb; float* C;
    if (blockIdx.z == 0)      { W = qw; bb = qb; C = g_q; }
    else if (blockIdx.z == 1) { W = kw; bb = kb; C = g_k; }
    else                      { W = vw; bb = vb; C = g_v; }
    gemm_body(g_x, W, bb, C, D_, blockIdx.x * 128, blockIdx.y * 256);
}

__global__ void __launch_bounds__(256, 1) out_gemm_kernel(
    const float* __restrict__ W, const float* __restrict__ bias,
    float* __restrict__ C)
{
    gemm_body(g_x, W, bias, C, V_, blockIdx.x * 128, blockIdx.y * 256);
}

// ---------------------------------------------------------------------------
// Attention: one block per (b, h). S=24, DH=64. Fused residual. float4 I/O.
// ---------------------------------------------------------------------------
__global__ void __launch_bounds__(256) attn_kernel()
{
    __shared__ float qs[S_][DH_];
    __shared__ float ks_[S_][DH_];
    __shared__ float vs[S_][DH_];
    __shared__ float sc[S_][S_];

    const int bh  = blockIdx.x;
    const int b   = bh >> 4;
    const int h   = bh & 15;
    const int tid = threadIdx.x;

    for (int idx = tid; idx < S_ * DH_ / 4; idx += 256) {
        int s = idx >> 4, c4 = (idx & 15) * 4;
        size_t off = ((size_t)s * B_ + b) * D_ + h * DH_ + c4;
        *(float4*)&qs[s][c4]  = *(const float4*)(g_q + off);
        *(float4*)&ks_[s][c4] = *(const float4*)(g_k + off);
        *(float4*)&vs[s][c4]  = *(const float4*)(g_v + off);
    }
    __syncthreads();

    const float scale = 0.03125f;   // 1/sqrt(1024)
    for (int idx = tid; idx < S_ * S_; idx += 256) {
        int s = idx / S_, t = idx % S_;
        float dot = 0.f;
        #pragma unroll
        for (int d = 0; d < DH_; d++) dot = fmaf(qs[s][d], ks_[t][d], dot);
        sc[s][t] = dot * scale;
    }
    __syncthreads();

    if (tid < S_) {
        float m = -1e30f;
        #pragma unroll
        for (int t = 0; t < S_; t++) m = fmaxf(m, sc[tid][t]);
        float sum = 0.f;
        #pragma unroll
        for (int t = 0; t < S_; t++) {
            float e = expf(sc[tid][t] - m);
            sc[tid][t] = e;
            sum += e;
        }
        float inv = 1.f / sum;
        #pragma unroll
        for (int t = 0; t < S_; t++) sc[tid][t] *= inv;
    }
    __syncthreads();

    for (int idx = tid; idx < S_ * DH_ / 4; idx += 256) {
        int s = idx >> 4, c4 = (idx & 15) * 4;
        float4 o = {0.f, 0.f, 0.f, 0.f};
        #pragma unroll
        for (int t = 0; t < S_; t++) {
            float p = sc[s][t];
            float4 vv = *(const float4*)&vs[t][c4];
            o.x = fmaf(p, vv.x, o.x);
            o.y = fmaf(p, vv.y, o.y);
            o.z = fmaf(p, vv.z, o.z);
            o.w = fmaf(p, vv.w, o.w);
        }
        size_t off = ((size_t)s * B_ + b) * D_ + h * DH_ + c4;
        float4 xv = *(const float4*)(g_x + off);
        xv.x += o.x; xv.y += o.y; xv.z += o.z; xv.w += o.w;
        *(float4*)(g_x + off) = xv;
    }
}

// ---------------------------------------------------------------------------
// Launch
// ---------------------------------------------------------------------------
extern "C" void kernel_launch(void* const* d_in, const int* in_sizes, int n_in,
                              void* d_out, int out_size)
{
    const int*   inp = (const int*)  d_in[0];
    const float* tok = (const float*)d_in[2];
    const float* pe  = (const float*)d_in[3];
    const float* qw  = (const float*)d_in[4];
    const float* qb  = (const float*)d_in[5];
    const float* kw  = (const float*)d_in[6];
    const float* kb  = (const float*)d_in[7];
    const float* vw  = (const float*)d_in[8];
    const float* vb  = (const float*)d_in[9];
    const float* ow  = (const float*)d_in[10];
    const float* ob  = (const float*)d_in[11];
    float* out = (float*)d_out;

    cudaFuncSetAttribute(qkv_gemm_kernel, cudaFuncAttributeMaxDynamicSharedMemorySize, SMEM_BYTES);
    cudaFuncSetAttribute(out_gemm_kernel, cudaFuncAttributeMaxDynamicSharedMemorySize, SMEM_BYTES);

    embed_kernel<<<NTOK * D_ / 4 / 256, 256>>>(inp, tok, pe);

    for (int l = 0; l < L_; l++) {
        const size_t wo = (size_t)l * D_ * D_;
        const size_t bo = (size_t)l * D_;
        qkv_gemm_kernel<<<dim3(NTOK / 128, D_ / 256, 3), 256, SMEM_BYTES>>>(
            qw + wo, qb + bo, kw + wo, kb + bo, vw + wo, vb + bo);
        attn_kernel<<<B_ * H_, 256>>>();
    }

    out_gemm_kernel<<<dim3(NTOK / 128, V_ / 256), 256, SMEM_BYTES>>>(ow, ob, out);
}

// round 6
// speedup vs baseline: 1.0876x; 1.0690x over previous
#include <cuda_runtime.h>
#include <cstdint>

#define S_   24
#define B_   256
#define D_   1024
#define H_   16
#define DH_  64
#define L_   12
#define V_   32000
#define NTOK (S_ * B_)   // 6144

// Scratch (allocation-free rule: __device__ globals)
__device__ float    g_x [NTOK * D_];    // fp32 residual stream
__device__ uint32_t g_xr[NTOK * D_];    // tf32-rounded copy (GEMM A operand)
__device__ float    g_q [NTOK * D_];
__device__ float    g_k [NTOK * D_];
__device__ float    g_v [NTOK * D_];
__device__ uint32_t g_wq[D_ * D_];      // tf32-rounded weights (per layer)
__device__ uint32_t g_wk[D_ * D_];
__device__ uint32_t g_wv[D_ * D_];
__device__ uint32_t g_wo[(size_t)V_ * D_];

// ---------------------------------------------------------------------------
// Helpers
// ---------------------------------------------------------------------------
__device__ __forceinline__ uint32_t smem_u32(const void* p) {
    uint32_t a;
    asm("{ .reg .u64 t; cvta.to.shared.u64 t, %1; cvt.u32.u64 %0, t; }" : "=r"(a) : "l"(p));
    return a;
}
__device__ __forceinline__ uint32_t f2tf(float x) {
    uint32_t y;
    asm("cvt.rna.tf32.f32 %0, %1;" : "=r"(y) : "f"(x));
    return y;
}
__device__ __forceinline__ uint32_t ldsu(uint32_t a) {
    uint32_t v;
    asm volatile("ld.shared.b32 %0, [%1];" : "=r"(v) : "r"(a));
    return v;
}
__device__ __forceinline__ void mma_tf32(float* d, const uint32_t* a, const uint32_t* b) {
    asm volatile(
        "mma.sync.aligned.m16n8k8.row.col.f32.tf32.tf32.f32 "
        "{%0,%1,%2,%3}, {%4,%5,%6,%7}, {%8,%9}, {%0,%1,%2,%3};"
        : "+f"(d[0]), "+f"(d[1]), "+f"(d[2]), "+f"(d[3])
        : "r"(a[0]), "r"(a[1]), "r"(a[2]), "r"(a[3]), "r"(b[0]), "r"(b[1]));
}
#define CPA16(dst, src) asm volatile("cp.async.ca.shared.global [%0], [%1], 16;" \
    :: "r"(dst), "l"(src) : "memory")
#define CPA_COMMIT() asm volatile("cp.async.commit_group;" ::: "memory")
#define CPA_WAIT2()  asm volatile("cp.async.wait_group 2;" ::: "memory")

// ---------------------------------------------------------------------------
// tf32 conversion kernels (RNA pre-rounding; keeps numerics of prior rounds)
// ---------------------------------------------------------------------------
__global__ void __launch_bounds__(256) conv_qkv_kernel(
    const float* __restrict__ qw, const float* __restrict__ kw,
    const float* __restrict__ vw)
{
    const float* src;
    uint32_t* dst;
    if (blockIdx.z == 0)      { src = qw; dst = g_wq; }
    else if (blockIdx.z == 1) { src = kw; dst = g_wk; }
    else                      { src = vw; dst = g_wv; }
    size_t i = ((size_t)blockIdx.x * 256 + threadIdx.x) * 4;
    float4 v = *(const float4*)(src + i);
    uint4 o = { f2tf(v.x), f2tf(v.y), f2tf(v.z), f2tf(v.w) };
    *(uint4*)(dst + i) = o;
}

__global__ void __launch_bounds__(256) conv_out_kernel(const float* __restrict__ w)
{
    size_t i = ((size_t)blockIdx.x * 256 + threadIdx.x) * 4;
    float4 v = *(const float4*)(w + i);
    uint4 o = { f2tf(v.x), f2tf(v.y), f2tf(v.z), f2tf(v.w) };
    *(uint4*)(g_wo + i) = o;
}

// ---------------------------------------------------------------------------
// Embedding: writes fp32 stream and tf32-rounded copy
// ---------------------------------------------------------------------------
__global__ void __launch_bounds__(256) embed_kernel(
    const int* __restrict__ inp,
    const float* __restrict__ tok,
    const float* __restrict__ pe)
{
    int e4 = blockIdx.x * 256 + threadIdx.x;
    int e  = e4 * 4;
    int n  = e / D_;
    int d  = e % D_;
    int s  = n / B_;
    int t  = inp[n];
    float4 a = *(const float4*)(tok + (size_t)t * D_ + d);
    float4 p = *(const float4*)(pe + (size_t)s * D_ + d);
    a.x += p.x; a.y += p.y; a.z += p.z; a.w += p.w;
    *(float4*)(g_x + e) = a;
    uint4 r = { f2tf(a.x), f2tf(a.y), f2tf(a.z), f2tf(a.w) };
    *(uint4*)(g_xr + e) = r;
}

// ---------------------------------------------------------------------------
// TF32 mma GEMM, cp.async 4-stage, pre-rounded operands (no cvt in loop).
// C[m,n] = sum_k A[m,k]*B[n,k] + bias[n]
// Block tile 128x128, BK=16, 8 warps @ 64x32 warp tiles, 2 CTAs/SM.
// Stage: A 8KB + B 8KB = 16KB; 4 stages = 64KB.
// Row = 16 floats = 4 x 16B chunks; chunk c stored at c ^ ((row>>1)&3)
//   -> all fragment scalar LDS conflict-free (verified by bank enumeration).
// ---------------------------------------------------------------------------
#define BK_    16
#define KT     (D_ / BK_)   // 64
#define STAGEB 16384u
#define SMEM_BYTES (4 * 16384)

__device__ __forceinline__ void gemm_body(
    const uint32_t* __restrict__ A, const uint32_t* __restrict__ Bw,
    const float* __restrict__ bias, float* __restrict__ C,
    int N, int bm, int bn)
{
    extern __shared__ char smem[];
    const uint32_t sbase = smem_u32(smem);

    const int tid  = threadIdx.x;
    const int lane = tid & 31;
    const int wid  = tid >> 5;
    const int grp  = lane >> 2;      // 0..7
    const int tig  = lane & 3;       // 0..3
    const int wm   = wid >> 2;       // 0..1  (64-row half)
    const int wn   = wid & 3;        // 0..3  (32-col quarter)

    // ---- producer mapping: 2 chunks of A + 2 chunks of B per thread ----
    const int pm = tid >> 1;                 // row 0..127
    const int pu = (tid & 1) * 2;            // chunk pair 0 or 2
    const uint32_t xr = (uint32_t)((pm >> 1) & 3);
    const uint32_t off0 = (uint32_t)pm * 64u + ((((uint32_t)pu    ) ^ xr) << 4);
    const uint32_t off1 = (uint32_t)pm * 64u + ((((uint32_t)pu + 1) ^ xr) << 4);
    const uint32_t* agp = A  + (size_t)(bm + pm) * D_ + pu * 4;
    const uint32_t* bgp = Bw + (size_t)(bn + pm) * D_ + pu * 4;

    #define ISSUE(t) do {                                                      \
        const uint32_t stb = sbase + (uint32_t)((t) & 3) * STAGEB;             \
        const uint32_t* a0 = agp + (t) * BK_;                                  \
        CPA16(stb + off0, a0);                                                 \
        CPA16(stb + off1, a0 + 4);                                             \
        const uint32_t* b0 = bgp + (t) * BK_;                                  \
        CPA16(stb + 8192u + off0, b0);                                         \
        CPA16(stb + 8192u + off1, b0 + 4);                                     \
    } while (0)

    float acc[4][4][4];
    #pragma unroll
    for (int i = 0; i < 4; i++)
        #pragma unroll
        for (int j = 0; j < 4; j++)
            #pragma unroll
            for (int c = 0; c < 4; c++) acc[i][j][c] = 0.f;

    ISSUE(0); CPA_COMMIT();
    ISSUE(1); CPA_COMMIT();
    ISSUE(2); CPA_COMMIT();

    // consumer address precompute
    uint32_t abase[4][2], axor[4][2];
    #pragma unroll
    for (int i = 0; i < 4; i++) {
        int m0 = wm * 64 + i * 16 + grp;
        int m1 = m0 + 8;
        abase[i][0] = (uint32_t)m0 * 64u + (uint32_t)tig * 4u;
        abase[i][1] = (uint32_t)m1 * 64u + (uint32_t)tig * 4u;
        axor[i][0]  = (uint32_t)((m0 >> 1) & 3);
        axor[i][1]  = (uint32_t)((m1 >> 1) & 3);
    }
    uint32_t bbase[4], bxor[4];
    #pragma unroll
    for (int j = 0; j < 4; j++) {
        int n0 = wn * 32 + j * 8 + grp;
        bbase[j] = (uint32_t)n0 * 64u + (uint32_t)tig * 4u;
        bxor[j]  = (uint32_t)((n0 >> 1) & 3);
    }

    for (int t = 0; t < KT; t++) {
        CPA_WAIT2();
        __syncthreads();

        const uint32_t ab = sbase + (uint32_t)(t & 3) * STAGEB;
        const uint32_t bb = ab + 8192u;

        #pragma unroll
        for (int ks = 0; ks < 2; ks++) {
            const uint32_t c0 = (uint32_t)(ks * 2);
            uint32_t af[4][4];
            #pragma unroll
            for (int i = 0; i < 4; i++) {
                af[i][0] = ldsu(ab + abase[i][0] + (((c0    ) ^ axor[i][0]) << 4));
                af[i][1] = ldsu(ab + abase[i][1] + (((c0    ) ^ axor[i][1]) << 4));
                af[i][2] = ldsu(ab + abase[i][0] + (((c0 + 1) ^ axor[i][0]) << 4));
                af[i][3] = ldsu(ab + abase[i][1] + (((c0 + 1) ^ axor[i][1]) << 4));
            }
            uint32_t bf[4][2];
            #pragma unroll
            for (int j = 0; j < 4; j++) {
                bf[j][0] = ldsu(bb + bbase[j] + (((c0    ) ^ bxor[j]) << 4));
                bf[j][1] = ldsu(bb + bbase[j] + (((c0 + 1) ^ bxor[j]) << 4));
            }
            #pragma unroll
            for (int i = 0; i < 4; i++)
                #pragma unroll
                for (int j = 0; j < 4; j++)
                    mma_tf32(acc[i][j], af[i], bf[j]);
        }

        if (t + 3 < KT) ISSUE(t + 3);
        CPA_COMMIT();
    }

    // ---- epilogue ----
    #pragma unroll
    for (int i = 0; i < 4; i++) {
        const int r0 = bm + wm * 64 + i * 16 + grp;
        #pragma unroll
        for (int j = 0; j < 4; j++) {
            const int col = bn + wn * 32 + j * 8 + tig * 2;
            float2 bv = *(const float2*)(bias + col);
            float2 v0 = { acc[i][j][0] + bv.x, acc[i][j][1] + bv.y };
            float2 v1 = { acc[i][j][2] + bv.x, acc[i][j][3] + bv.y };
            *(float2*)(C + (size_t)r0 * N + col)       = v0;
            *(float2*)(C + (size_t)(r0 + 8) * N + col) = v1;
        }
    }
    #undef ISSUE
}

__global__ void __launch_bounds__(256, 2) qkv_gemm_kernel(
    const float* __restrict__ qb, const float* __restrict__ kb,
    const float* __restrict__ vb)
{
    const uint32_t* W; const float* bb; float* C;
    if (blockIdx.z == 0)      { W = g_wq; bb = qb; C = g_q; }
    else if (blockIdx.z == 1) { W = g_wk; bb = kb; C = g_k; }
    else                      { W = g_wv; bb = vb; C = g_v; }
    gemm_body(g_xr, W, bb, C, D_, blockIdx.x * 128, blockIdx.y * 128);
}

__global__ void __launch_bounds__(256, 2) out_gemm_kernel(
    const float* __restrict__ bias, float* __restrict__ C)
{
    gemm_body(g_xr, g_wo, bias, C, V_, blockIdx.x * 128, blockIdx.y * 128);
}

// ---------------------------------------------------------------------------
// Attention: one block per (b, h). S=24, DH=64. Fused residual.
// Writes both fp32 stream and tf32-rounded copy.
// ---------------------------------------------------------------------------
__global__ void __launch_bounds__(256) attn_kernel()
{
    __shared__ float qs[S_][DH_];
    __shared__ float ks_[S_][DH_];
    __shared__ float vs[S_][DH_];
    __shared__ float sc[S_][S_];

    const int bh  = blockIdx.x;
    const int b   = bh >> 4;
    const int h   = bh & 15;
    const int tid = threadIdx.x;

    for (int idx = tid; idx < S_ * DH_ / 4; idx += 256) {
        int s = idx >> 4, c4 = (idx & 15) * 4;
        size_t off = ((size_t)s * B_ + b) * D_ + h * DH_ + c4;
        *(float4*)&qs[s][c4]  = *(const float4*)(g_q + off);
        *(float4*)&ks_[s][c4] = *(const float4*)(g_k + off);
        *(float4*)&vs[s][c4]  = *(const float4*)(g_v + off);
    }
    __syncthreads();

    const float scale = 0.03125f;   // 1/sqrt(1024)
    for (int idx = tid; idx < S_ * S_; idx += 256) {
        int s = idx / S_, t = idx % S_;
        float dot = 0.f;
        #pragma unroll
        for (int d = 0; d < DH_; d++) dot = fmaf(qs[s][d], ks_[t][d], dot);
        sc[s][t] = dot * scale;
    }
    __syncthreads();

    if (tid < S_) {
        float m = -1e30f;
        #pragma unroll
        for (int t = 0; t < S_; t++) m = fmaxf(m, sc[tid][t]);
        float sum = 0.f;
        #pragma unroll
        for (int t = 0; t < S_; t++) {
            float e = expf(sc[tid][t] - m);
            sc[tid][t] = e;
            sum += e;
        }
        float inv = 1.f / sum;
        #pragma unroll
        for (int t = 0; t < S_; t++) sc[tid][t] *= inv;
    }
    __syncthreads();

    for (int idx = tid; idx < S_ * DH_ / 4; idx += 256) {
        int s = idx >> 4, c4 = (idx & 15) * 4;
        float4 o = {0.f, 0.f, 0.f, 0.f};
        #pragma unroll
        for (int t = 0; t < S_; t++) {
            float p = sc[s][t];
            float4 vv = *(const float4*)&vs[t][c4];
            o.x = fmaf(p, vv.x, o.x);
            o.y = fmaf(p, vv.y, o.y);
            o.z = fmaf(p, vv.z, o.z);
            o.w = fmaf(p, vv.w, o.w);
        }
        size_t off = ((size_t)s * B_ + b) * D_ + h * DH_ + c4;
        float4 xv = *(const float4*)(g_x + off);
        xv.x += o.x; xv.y += o.y; xv.z += o.z; xv.w += o.w;
        *(float4*)(g_x + off) = xv;
        uint4 r = { f2tf(xv.x), f2tf(xv.y), f2tf(xv.z), f2tf(xv.w) };
        *(uint4*)(g_xr + off) = r;
    }
}

// ---------------------------------------------------------------------------
// Launch
// ---------------------------------------------------------------------------
extern "C" void kernel_launch(void* const* d_in, const int* in_sizes, int n_in,
                              void* d_out, int out_size)
{
    const int*   inp = (const int*)  d_in[0];
    const float* tok = (const float*)d_in[2];
    const float* pe  = (const float*)d_in[3];
    const float* qw  = (const float*)d_in[4];
    const float* qb  = (const float*)d_in[5];
    const float* kw  = (const float*)d_in[6];
    const float* kb  = (const float*)d_in[7];
    const float* vw  = (const float*)d_in[8];
    const float* vb  = (const float*)d_in[9];
    const float* ow  = (const float*)d_in[10];
    const float* ob  = (const float*)d_in[11];
    float* out = (float*)d_out;

    cudaFuncSetAttribute(qkv_gemm_kernel, cudaFuncAttributeMaxDynamicSharedMemorySize, SMEM_BYTES);
    cudaFuncSetAttribute(out_gemm_kernel, cudaFuncAttributeMaxDynamicSharedMemorySize, SMEM_BYTES);

    embed_kernel<<<NTOK * D_ / 4 / 256, 256>>>(inp, tok, pe);
    conv_out_kernel<<<(size_t)V_ * D_ / 4 / 256, 256>>>(ow);

    for (int l = 0; l < L_; l++) {
        const size_t wo = (size_t)l * D_ * D_;
        const size_t bo = (size_t)l * D_;
        conv_qkv_kernel<<<dim3(D_ * D_ / 4 / 256, 1, 3), 256>>>(
            qw + wo, kw + wo, vw + wo);
        qkv_gemm_kernel<<<dim3(NTOK / 128, D_ / 128, 3), 256, SMEM_BYTES>>>(
            qb + bo, kb + bo, vb + bo);
        attn_kernel<<<B_ * H_, 256>>>();
    }

    out_gemm_kernel<<<dim3(NTOK / 128, V_ / 128), 256, SMEM_BYTES>>>(ob, out);
}

// round 7
// speedup vs baseline: 1.1886x; 1.0929x over previous
#include <cuda_runtime.h>
#include <cstdint>

#define S_   24
#define B_   256
#define D_   1024
#define H_   16
#define DH_  64
#define L_   12
#define V_   32000
#define NTOK (S_ * B_)   // 6144

// Scratch (allocation-free rule: __device__ globals)
__device__ float    g_x [NTOK * D_];    // fp32 residual stream
__device__ uint32_t g_xr[NTOK * D_];    // tf32-rounded copy (GEMM A operand)
__device__ float    g_q [NTOK * D_];
__device__ float    g_k [NTOK * D_];
__device__ float    g_v [NTOK * D_];
__device__ uint32_t g_wq[D_ * D_];      // tf32-rounded weights (per layer)
__device__ uint32_t g_wk[D_ * D_];
__device__ uint32_t g_wv[D_ * D_];
__device__ uint32_t g_wo[(size_t)V_ * D_];

// ---------------------------------------------------------------------------
// Helpers
// ---------------------------------------------------------------------------
__device__ __forceinline__ uint32_t smem_u32(const void* p) {
    uint32_t a;
    asm("{ .reg .u64 t; cvta.to.shared.u64 t, %1; cvt.u32.u64 %0, t; }" : "=r"(a) : "l"(p));
    return a;
}
__device__ __forceinline__ uint32_t f2tf(float x) {
    uint32_t y;
    asm("cvt.rna.tf32.f32 %0, %1;" : "=r"(y) : "f"(x));
    return y;
}
__device__ __forceinline__ uint32_t ldsu(uint32_t a) {
    uint32_t v;
    asm volatile("ld.shared.b32 %0, [%1];" : "=r"(v) : "r"(a));
    return v;
}
__device__ __forceinline__ void mma_tf32(float* d, const uint32_t* a, const uint32_t* b) {
    asm volatile(
        "mma.sync.aligned.m16n8k8.row.col.f32.tf32.tf32.f32 "
        "{%0,%1,%2,%3}, {%4,%5,%6,%7}, {%8,%9}, {%0,%1,%2,%3};"
        : "+f"(d[0]), "+f"(d[1]), "+f"(d[2]), "+f"(d[3])
        : "r"(a[0]), "r"(a[1]), "r"(a[2]), "r"(a[3]), "r"(b[0]), "r"(b[1]));
}
#define CPA16(dst, src) asm volatile("cp.async.cg.shared.global [%0], [%1], 16;" \
    :: "r"(dst), "l"(src) : "memory")
#define CPA_COMMIT() asm volatile("cp.async.commit_group;" ::: "memory")
#define CPA_WAIT2()  asm volatile("cp.async.wait_group 2;" ::: "memory")

// ---------------------------------------------------------------------------
// tf32 conversion kernels (RNA pre-rounding; keeps numerics of prior rounds)
// ---------------------------------------------------------------------------
__global__ void __launch_bounds__(256) conv_qkv_kernel(
    const float* __restrict__ qw, const float* __restrict__ kw,
    const float* __restrict__ vw)
{
    const float* src;
    uint32_t* dst;
    if (blockIdx.z == 0)      { src = qw; dst = g_wq; }
    else if (blockIdx.z == 1) { src = kw; dst = g_wk; }
    else                      { src = vw; dst = g_wv; }
    size_t i = ((size_t)blockIdx.x * 256 + threadIdx.x) * 4;
    float4 v = *(const float4*)(src + i);
    uint4 o = { f2tf(v.x), f2tf(v.y), f2tf(v.z), f2tf(v.w) };
    *(uint4*)(dst + i) = o;
}

__global__ void __launch_bounds__(256) conv_out_kernel(const float* __restrict__ w)
{
    size_t i = ((size_t)blockIdx.x * 256 + threadIdx.x) * 4;
    float4 v = *(const float4*)(w + i);
    uint4 o = { f2tf(v.x), f2tf(v.y), f2tf(v.z), f2tf(v.w) };
    *(uint4*)(g_wo + i) = o;
}

// ---------------------------------------------------------------------------
// Embedding: writes fp32 stream and tf32-rounded copy
// ---------------------------------------------------------------------------
__global__ void __launch_bounds__(256) embed_kernel(
    const int* __restrict__ inp,
    const float* __restrict__ tok,
    const float* __restrict__ pe)
{
    int e4 = blockIdx.x * 256 + threadIdx.x;
    int e  = e4 * 4;
    int n  = e / D_;
    int d  = e % D_;
    int s  = n / B_;
    int t  = inp[n];
    float4 a = *(const float4*)(tok + (size_t)t * D_ + d);
    float4 p = *(const float4*)(pe + (size_t)s * D_ + d);
    a.x += p.x; a.y += p.y; a.z += p.z; a.w += p.w;
    *(float4*)(g_x + e) = a;
    uint4 r = { f2tf(a.x), f2tf(a.y), f2tf(a.z), f2tf(a.w) };
    *(uint4*)(g_xr + e) = r;
}

// ---------------------------------------------------------------------------
// TF32 mma GEMM, cp.async.cg 4-stage, pre-rounded operands.
// Block tile 128x128, BK=16, 8 warps @ 64x32 warp tiles, 2 CTAs/SM.
// Intra-tile pipelining: A0,B0,A1 -> issue next cp.async -> mma0 -> B1 -> mma1
// ---------------------------------------------------------------------------
#define BK_    16
#define KT     (D_ / BK_)   // 64
#define STAGEB 16384u
#define SMEM_BYTES (4 * 16384)

__device__ __forceinline__ void gemm_body(
    const uint32_t* __restrict__ A, const uint32_t* __restrict__ Bw,
    const float* __restrict__ bias, float* __restrict__ C,
    int N, int bm, int bn)
{
    extern __shared__ char smem[];
    const uint32_t sbase = smem_u32(smem);

    const int tid  = threadIdx.x;
    const int lane = tid & 31;
    const int wid  = tid >> 5;
    const int grp  = lane >> 2;      // 0..7
    const int tig  = lane & 3;       // 0..3
    const int wm   = wid >> 2;       // 0..1  (64-row half)
    const int wn   = wid & 3;        // 0..3  (32-col quarter)

    // ---- producer mapping: 2 chunks of A + 2 chunks of B per thread ----
    const int pm = tid >> 1;                 // row 0..127
    const int pu = (tid & 1) * 2;            // chunk pair 0 or 2
    const uint32_t xr = (uint32_t)((pm >> 1) & 3);
    const uint32_t off0 = (uint32_t)pm * 64u + ((((uint32_t)pu    ) ^ xr) << 4);
    const uint32_t off1 = (uint32_t)pm * 64u + ((((uint32_t)pu + 1) ^ xr) << 4);
    const uint32_t* agp = A  + (size_t)(bm + pm) * D_ + pu * 4;
    const uint32_t* bgp = Bw + (size_t)(bn + pm) * D_ + pu * 4;

    #define ISSUE(t) do {                                                      \
        const uint32_t stb = sbase + (uint32_t)((t) & 3) * STAGEB;             \
        const uint32_t* a0 = agp + (t) * BK_;                                  \
        CPA16(stb + off0, a0);                                                 \
        CPA16(stb + off1, a0 + 4);                                             \
        const uint32_t* b0 = bgp + (t) * BK_;                                  \
        CPA16(stb + 8192u + off0, b0);                                         \
        CPA16(stb + 8192u + off1, b0 + 4);                                     \
    } while (0)

    float acc[4][4][4];
    #pragma unroll
    for (int i = 0; i < 4; i++)
        #pragma unroll
        for (int j = 0; j < 4; j++)
            #pragma unroll
            for (int c = 0; c < 4; c++) acc[i][j][c] = 0.f;

    ISSUE(0); CPA_COMMIT();
    ISSUE(1); CPA_COMMIT();
    ISSUE(2); CPA_COMMIT();

    // consumer address precompute
    uint32_t abase[4][2], axor[4][2];
    #pragma unroll
    for (int i = 0; i < 4; i++) {
        int m0 = wm * 64 + i * 16 + grp;
        int m1 = m0 + 8;
        abase[i][0] = (uint32_t)m0 * 64u + (uint32_t)tig * 4u;
        abase[i][1] = (uint32_t)m1 * 64u + (uint32_t)tig * 4u;
        axor[i][0]  = (uint32_t)((m0 >> 1) & 3);
        axor[i][1]  = (uint32_t)((m1 >> 1) & 3);
    }
    uint32_t bbase[4], bxor[4];
    #pragma unroll
    for (int j = 0; j < 4; j++) {
        int n0 = wn * 32 + j * 8 + grp;
        bbase[j] = (uint32_t)n0 * 64u + (uint32_t)tig * 4u;
        bxor[j]  = (uint32_t)((n0 >> 1) & 3);
    }

    for (int t = 0; t < KT; t++) {
        CPA_WAIT2();
        __syncthreads();

        // issue stage t+3 NOW (writes stage (t-1)&3, consumed last iter,
        // ordered by the barrier above) — fills LSU while frags load.
        if (t + 3 < KT) ISSUE(t + 3);

        const uint32_t ab = sbase + (uint32_t)(t & 3) * STAGEB;
        const uint32_t bb = ab + 8192u;

        // ---- pipelined 2x k8 slices ----
        uint32_t af0[4][4], af1[4][4], bf0[4][2], bf1[4][2];
        #pragma unroll
        for (int i = 0; i < 4; i++) {
            af0[i][0] = ldsu(ab + abase[i][0] + (((0u) ^ axor[i][0]) << 4));
            af0[i][1] = ldsu(ab + abase[i][1] + (((0u) ^ axor[i][1]) << 4));
            af0[i][2] = ldsu(ab + abase[i][0] + (((1u) ^ axor[i][0]) << 4));
            af0[i][3] = ldsu(ab + abase[i][1] + (((1u) ^ axor[i][1]) << 4));
        }
        #pragma unroll
        for (int j = 0; j < 4; j++) {
            bf0[j][0] = ldsu(bb + bbase[j] + (((0u) ^ bxor[j]) << 4));
            bf0[j][1] = ldsu(bb + bbase[j] + (((1u) ^ bxor[j]) << 4));
        }
        #pragma unroll
        for (int i = 0; i < 4; i++) {
            af1[i][0] = ldsu(ab + abase[i][0] + (((2u) ^ axor[i][0]) << 4));
            af1[i][1] = ldsu(ab + abase[i][1] + (((2u) ^ axor[i][1]) << 4));
            af1[i][2] = ldsu(ab + abase[i][0] + (((3u) ^ axor[i][0]) << 4));
            af1[i][3] = ldsu(ab + abase[i][1] + (((3u) ^ axor[i][1]) << 4));
        }
        #pragma unroll
        for (int i = 0; i < 4; i++)
            #pragma unroll
            for (int j = 0; j < 4; j++)
                mma_tf32(acc[i][j], af0[i], bf0[j]);
        #pragma unroll
        for (int j = 0; j < 4; j++) {
            bf1[j][0] = ldsu(bb + bbase[j] + (((2u) ^ bxor[j]) << 4));
            bf1[j][1] = ldsu(bb + bbase[j] + (((3u) ^ bxor[j]) << 4));
        }
        #pragma unroll
        for (int i = 0; i < 4; i++)
            #pragma unroll
            for (int j = 0; j < 4; j++)
                mma_tf32(acc[i][j], af1[i], bf1[j]);

        CPA_COMMIT();
    }

    // ---- epilogue ----
    #pragma unroll
    for (int i = 0; i < 4; i++) {
        const int r0 = bm + wm * 64 + i * 16 + grp;
        #pragma unroll
        for (int j = 0; j < 4; j++) {
            const int col = bn + wn * 32 + j * 8 + tig * 2;
            float2 bv = *(const float2*)(bias + col);
            float2 v0 = { acc[i][j][0] + bv.x, acc[i][j][1] + bv.y };
            float2 v1 = { acc[i][j][2] + bv.x, acc[i][j][3] + bv.y };
            *(float2*)(C + (size_t)r0 * N + col)       = v0;
            *(float2*)(C + (size_t)(r0 + 8) * N + col) = v1;
        }
    }
    #undef ISSUE
}

__global__ void __launch_bounds__(256, 2) qkv_gemm_kernel(
    const float* __restrict__ qb, const float* __restrict__ kb,
    const float* __restrict__ vb)
{
    const uint32_t* W; const float* bb; float* C;
    if (blockIdx.z == 0)      { W = g_wq; bb = qb; C = g_q; }
    else if (blockIdx.z == 1) { W = g_wk; bb = kb; C = g_k; }
    else                      { W = g_wv; bb = vb; C = g_v; }
    gemm_body(g_xr, W, bb, C, D_, blockIdx.x * 128, blockIdx.y * 128);
}

__global__ void __launch_bounds__(256, 2) out_gemm_kernel(
    const float* __restrict__ bias, float* __restrict__ C)
{
    gemm_body(g_xr, g_wo, bias, C, V_, blockIdx.x * 128, blockIdx.y * 128);
}

// ---------------------------------------------------------------------------
// Attention: one block per (b, h). S=24, DH=64. Fused residual.
// ---------------------------------------------------------------------------
__global__ void __launch_bounds__(256) attn_kernel()
{
    __shared__ float qs[S_][DH_];
    __shared__ float ks_[S_][DH_];
    __shared__ float vs[S_][DH_];
    __shared__ float sc[S_][S_];

    const int bh  = blockIdx.x;
    const int b   = bh >> 4;
    const int h   = bh & 15;
    const int tid = threadIdx.x;

    for (int idx = tid; idx < S_ * DH_ / 4; idx += 256) {
        int s = idx >> 4, c4 = (idx & 15) * 4;
        size_t off = ((size_t)s * B_ + b) * D_ + h * DH_ + c4;
        *(float4*)&qs[s][c4]  = *(const float4*)(g_q + off);
        *(float4*)&ks_[s][c4] = *(const float4*)(g_k + off);
        *(float4*)&vs[s][c4]  = *(const float4*)(g_v + off);
    }
    __syncthreads();

    const float scale = 0.03125f;   // 1/sqrt(1024)
    for (int idx = tid; idx < S_ * S_; idx += 256) {
        int s = idx / S_, t = idx % S_;
        float dot = 0.f;
        #pragma unroll
        for (int d = 0; d < DH_; d++) dot = fmaf(qs[s][d], ks_[t][d], dot);
        sc[s][t] = dot * scale;
    }
    __syncthreads();

    if (tid < S_) {
        float m = -1e30f;
        #pragma unroll
        for (int t = 0; t < S_; t++) m = fmaxf(m, sc[tid][t]);
        float sum = 0.f;
        #pragma unroll
        for (int t = 0; t < S_; t++) {
            float e = expf(sc[tid][t] - m);
            sc[tid][t] = e;
            sum += e;
        }
        float inv = 1.f / sum;
        #pragma unroll
        for (int t = 0; t < S_; t++) sc[tid][t] *= inv;
    }
    __syncthreads();

    for (int idx = tid; idx < S_ * DH_ / 4; idx += 256) {
        int s = idx >> 4, c4 = (idx & 15) * 4;
        float4 o = {0.f, 0.f, 0.f, 0.f};
        #pragma unroll
        for (int t = 0; t < S_; t++) {
            float p = sc[s][t];
            float4 vv = *(const float4*)&vs[t][c4];
            o.x = fmaf(p, vv.x, o.x);
            o.y = fmaf(p, vv.y, o.y);
            o.z = fmaf(p, vv.z, o.z);
            o.w = fmaf(p, vv.w, o.w);
        }
        size_t off = ((size_t)s * B_ + b) * D_ + h * DH_ + c4;
        float4 xv = *(const float4*)(g_x + off);
        xv.x += o.x; xv.y += o.y; xv.z += o.z; xv.w += o.w;
        *(float4*)(g_x + off) = xv;
        uint4 r = { f2tf(xv.x), f2tf(xv.y), f2tf(xv.z), f2tf(xv.w) };
        *(uint4*)(g_xr + off) = r;
    }
}

// ---------------------------------------------------------------------------
// Launch
// ---------------------------------------------------------------------------
extern "C" void kernel_launch(void* const* d_in, const int* in_sizes, int n_in,
                              void* d_out, int out_size)
{
    const int*   inp = (const int*)  d_in[0];
    const float* tok = (const float*)d_in[2];
    const float* pe  = (const float*)d_in[3];
    const float* qw  = (const float*)d_in[4];
    const float* qb  = (const float*)d_in[5];
    const float* kw  = (const float*)d_in[6];
    const float* kb  = (const float*)d_in[7];
    const float* vw  = (const float*)d_in[8];
    const float* vb  = (const float*)d_in[9];
    const float* ow  = (const float*)d_in[10];
    const float* ob  = (const float*)d_in[11];
    float* out = (float*)d_out;

    cudaFuncSetAttribute(qkv_gemm_kernel, cudaFuncAttributeMaxDynamicSharedMemorySize, SMEM_BYTES);
    cudaFuncSetAttribute(out_gemm_kernel, cudaFuncAttributeMaxDynamicSharedMemorySize, SMEM_BYTES);

    embed_kernel<<<NTOK * D_ / 4 / 256, 256>>>(inp, tok, pe);
    conv_out_kernel<<<(size_t)V_ * D_ / 4 / 256, 256>>>(ow);

    for (int l = 0; l < L_; l++) {
        const size_t wo = (size_t)l * D_ * D_;
        const size_t bo = (size_t)l * D_;
        conv_qkv_kernel<<<dim3(D_ * D_ / 4 / 256, 1, 3), 256>>>(
            qw + wo, kw + wo, vw + wo);
        qkv_gemm_kernel<<<dim3(NTOK / 128, D_ / 128, 3), 256, SMEM_BYTES>>>(
            qb + bo, kb + bo, vb + bo);
        attn_kernel<<<B_ * H_, 256>>>();
    }

    out_gemm_kernel<<<dim3(NTOK / 128, V_ / 128), 256, SMEM_BYTES>>>(ob, out);
}

// round 8
// speedup vs baseline: 1.2772x; 1.0745x over previous
#include <cuda_runtime.h>
#include <cstdint>

#define S_   24
#define B_   256
#define D_   1024
#define H_   16
#define DH_  64
#define L_   12
#define V_   32000
#define NTOK (S_ * B_)   // 6144

// Scratch (allocation-free rule: __device__ globals)
__device__ float    g_x [NTOK * D_];        // fp32 residual stream
__device__ uint32_t g_xr[NTOK * D_];        // tf32-rounded copy (GEMM A operand)
__device__ float    g_q [NTOK * D_];
__device__ float    g_k [NTOK * D_];
__device__ float    g_v [NTOK * D_];
__device__ uint32_t g_wq[(size_t)L_ * D_ * D_];   // tf32-rounded weights, all layers
__device__ uint32_t g_wk[(size_t)L_ * D_ * D_];
__device__ uint32_t g_wv[(size_t)L_ * D_ * D_];
__device__ uint32_t g_wo[(size_t)V_ * D_];

// ---------------------------------------------------------------------------
// Helpers
// ---------------------------------------------------------------------------
__device__ __forceinline__ uint32_t smem_u32(const void* p) {
    uint32_t a;
    asm("{ .reg .u64 t; cvta.to.shared.u64 t, %1; cvt.u32.u64 %0, t; }" : "=r"(a) : "l"(p));
    return a;
}
__device__ __forceinline__ uint32_t f2tf(float x) {
    uint32_t y;
    asm("cvt.rna.tf32.f32 %0, %1;" : "=r"(y) : "f"(x));
    return y;
}
template <int IMM>
__device__ __forceinline__ uint32_t ldso(uint32_t a) {
    uint32_t v;
    asm volatile("ld.shared.b32 %0, [%1+%2];" : "=r"(v) : "r"(a), "n"(IMM));
    return v;
}
__device__ __forceinline__ void mma_tf32(float* d, const uint32_t* a, const uint32_t* b) {
    asm volatile(
        "mma.sync.aligned.m16n8k8.row.col.f32.tf32.tf32.f32 "
        "{%0,%1,%2,%3}, {%4,%5,%6,%7}, {%8,%9}, {%0,%1,%2,%3};"
        : "+f"(d[0]), "+f"(d[1]), "+f"(d[2]), "+f"(d[3])
        : "r"(a[0]), "r"(a[1]), "r"(a[2]), "r"(a[3]), "r"(b[0]), "r"(b[1]));
}
#define CPA16(dst, src) asm volatile("cp.async.cg.shared.global [%0], [%1], 16;" \
    :: "r"(dst), "l"(src) : "memory")
#define CPA_COMMIT() asm volatile("cp.async.commit_group;" ::: "memory")
#define CPA_WAIT1()  asm volatile("cp.async.wait_group 1;" ::: "memory")

// ---------------------------------------------------------------------------
// Weight conversion: all layers, all three matrices, one launch.
// ---------------------------------------------------------------------------
__global__ void __launch_bounds__(256) conv_all_kernel(
    const float* __restrict__ qw, const float* __restrict__ kw,
    const float* __restrict__ vw)
{
    const size_t lo = (size_t)blockIdx.y * D_ * D_;
    const float* src;
    uint32_t* dst;
    if (blockIdx.z == 0)      { src = qw + lo; dst = g_wq + lo; }
    else if (blockIdx.z == 1) { src = kw + lo; dst = g_wk + lo; }
    else                      { src = vw + lo; dst = g_wv + lo; }
    size_t i = ((size_t)blockIdx.x * 256 + threadIdx.x) * 4;
    float4 v = *(const float4*)(src + i);
    uint4 o = { f2tf(v.x), f2tf(v.y), f2tf(v.z), f2tf(v.w) };
    *(uint4*)(dst + i) = o;
}

__global__ void __launch_bounds__(256) conv_out_kernel(const float* __restrict__ w)
{
    size_t i = ((size_t)blockIdx.x * 256 + threadIdx.x) * 4;
    float4 v = *(const float4*)(w + i);
    uint4 o = { f2tf(v.x), f2tf(v.y), f2tf(v.z), f2tf(v.w) };
    *(uint4*)(g_wo + i) = o;
}

// ---------------------------------------------------------------------------
// Embedding
// ---------------------------------------------------------------------------
__global__ void __launch_bounds__(256) embed_kernel(
    const int* __restrict__ inp,
    const float* __restrict__ tok,
    const float* __restrict__ pe)
{
    int e4 = blockIdx.x * 256 + threadIdx.x;
    int e  = e4 * 4;
    int n  = e / D_;
    int d  = e % D_;
    int s  = n / B_;
    int t  = inp[n];
    float4 a = *(const float4*)(tok + (size_t)t * D_ + d);
    float4 p = *(const float4*)(pe + (size_t)s * D_ + d);
    a.x += p.x; a.y += p.y; a.z += p.z; a.w += p.w;
    *(float4*)(g_x + e) = a;
    uint4 r = { f2tf(a.x), f2tf(a.y), f2tf(a.z), f2tf(a.w) };
    *(uint4*)(g_xr + e) = r;
}

// ---------------------------------------------------------------------------
// TF32 mma GEMM, cp.async.cg 4-stage ring, cross-tile fragment prefetch.
// Block tile 128x128, BK=16, 8 warps @ 64x32 warp tiles, 2 CTAs/SM.
// ---------------------------------------------------------------------------
#define BK_    16
#define KT     (D_ / BK_)   // 64
#define STAGEB 16384u
#define SMEM_BYTES (4 * 16384)

template <bool STREAM>
__device__ __forceinline__ void gemm_body(
    const uint32_t* __restrict__ A, const uint32_t* __restrict__ Bw,
    const float* __restrict__ bias, float* __restrict__ C,
    int N, int bm, int bn)
{
    extern __shared__ char smem[];
    const uint32_t sbase = smem_u32(smem);

    const int tid  = threadIdx.x;
    const int lane = tid & 31;
    const int wid  = tid >> 5;
    const int grp  = lane >> 2;      // 0..7
    const int tig  = lane & 3;       // 0..3
    const int wm   = wid >> 2;       // 0..1
    const int wn   = wid & 3;        // 0..3

    // ---- producer mapping ----
    const int pm = tid >> 1;
    const int pu = (tid & 1) * 2;
    const uint32_t xr = (uint32_t)((pm >> 1) & 3);
    const uint32_t off0 = (uint32_t)pm * 64u + ((((uint32_t)pu    ) ^ xr) << 4);
    const uint32_t off1 = (uint32_t)pm * 64u + ((((uint32_t)pu + 1) ^ xr) << 4);
    const uint32_t* agp = A  + (size_t)(bm + pm) * D_ + pu * 4;
    const uint32_t* bgp = Bw + (size_t)(bn + pm) * D_ + pu * 4;

    #define ISSUE(t) do {                                                      \
        const uint32_t stb = sbase + (uint32_t)((t) & 3) * STAGEB;             \
        const uint32_t* a0 = agp + (t) * BK_;                                  \
        CPA16(stb + off0, a0);                                                 \
        CPA16(stb + off1, a0 + 4);                                             \
        const uint32_t* b0 = bgp + (t) * BK_;                                  \
        CPA16(stb + 8192u + off0, b0);                                         \
        CPA16(stb + 8192u + off1, b0 + 4);                                     \
    } while (0)

    float acc[4][4][4];
    #pragma unroll
    for (int i = 0; i < 4; i++)
        #pragma unroll
        for (int j = 0; j < 4; j++)
            #pragma unroll
            for (int c = 0; c < 4; c++) acc[i][j][c] = 0.f;

    // consumer folded bases: XOR bits live in bits 4..5 (free in the base)
    const int m00 = wm * 64 + grp;                 // i-invariant A row base
    const uint32_t a2 = (uint32_t)m00 * 64u + (uint32_t)tig * 4u
                      | (((uint32_t)((m00 >> 1) & 3)) << 4);
    const int n00 = wn * 32 + grp;                 // j-invariant B row base
    const uint32_t b2 = (uint32_t)n00 * 64u + (uint32_t)tig * 4u
                      | (((uint32_t)((n00 >> 1) & 3)) << 4);

    // A frag loader: slice s (chunks 2s, 2s+1); af[i] = {c0@m, c0@m+8, c1@m, c1@m+8}
    #define AF_LOAD(buf, ab, s) do {                                           \
        const uint32_t ra0 = (ab) + (a2 ^ (uint32_t)((2*(s))     << 4));       \
        const uint32_t ra1 = (ab) + (a2 ^ (uint32_t)((2*(s) + 1) << 4));       \
        buf[0][0] = ldso<0>(ra0);    buf[0][1] = ldso<512>(ra0);               \
        buf[0][2] = ldso<0>(ra1);    buf[0][3] = ldso<512>(ra1);               \
        buf[1][0] = ldso<1024>(ra0); buf[1][1] = ldso<1536>(ra0);              \
        buf[1][2] = ldso<1024>(ra1); buf[1][3] = ldso<1536>(ra1);              \
        buf[2][0] = ldso<2048>(ra0); buf[2][1] = ldso<2560>(ra0);              \
        buf[2][2] = ldso<2048>(ra1); buf[2][3] = ldso<2560>(ra1);              \
        buf[3][0] = ldso<3072>(ra0); buf[3][1] = ldso<3584>(ra0);              \
        buf[3][2] = ldso<3072>(ra1); buf[3][3] = ldso<3584>(ra1);              \
    } while (0)

    #define BF_LOAD(buf, bb, s) do {                                           \
        const uint32_t rb0 = (bb) + (b2 ^ (uint32_t)((2*(s))     << 4));       \
        const uint32_t rb1 = (bb) + (b2 ^ (uint32_t)((2*(s) + 1) << 4));       \
        buf[0][0] = ldso<0>(rb0);    buf[0][1] = ldso<0>(rb1);                 \
        buf[1][0] = ldso<512>(rb0);  buf[1][1] = ldso<512>(rb1);               \
        buf[2][0] = ldso<1024>(rb0); buf[2][1] = ldso<1024>(rb1);              \
        buf[3][0] = ldso<1536>(rb0); buf[3][1] = ldso<1536>(rb1);              \
    } while (0)

    #define MMA_SLICE(af, bf)                                                  \
        _Pragma("unroll") for (int i = 0; i < 4; i++)                          \
            _Pragma("unroll") for (int j = 0; j < 4; j++)                      \
                mma_tf32(acc[i][j], af[i], bf[j]);

    // prologue: stages 0..2 in flight; stages 0,1 complete + visible
    ISSUE(0); CPA_COMMIT();
    ISSUE(1); CPA_COMMIT();
    ISSUE(2); CPA_COMMIT();
    CPA_WAIT1();
    __syncthreads();

    uint32_t afc[4][4], afn[4][4], bf[4][2];
    AF_LOAD(afc, sbase, 0);                 // tile 0 slice 0 A-frags

    for (int t = 0; t < KT; t++) {
        const uint32_t ab   = sbase + (uint32_t)(t & 3) * STAGEB;
        const uint32_t bb   = ab + 8192u;
        const uint32_t ab_n = sbase + (uint32_t)((t + 1) & 3) * STAGEB;

        if (t + 3 < KT) ISSUE(t + 3);
        CPA_COMMIT();

        // slice 0: afc ready from previous iter; only B loads on critical path
        BF_LOAD(bf, bb, 0);
        AF_LOAD(afn, ab, 1);                // tile t slice 1
        MMA_SLICE(afc, bf);
        // slice 1
        BF_LOAD(bf, bb, 1);
        MMA_SLICE(afn, bf);
        // prefetch tile t+1 slice 0 A (stage t+1 complete+visible by invariant;
        // final iter reads stale-but-valid smem, result unused)
        AF_LOAD(afc, ab_n, 0);

        CPA_WAIT1();                        // stage t+2 complete
        __syncthreads();                    // ... and visible to all
    }

    // ---- epilogue ----
    #pragma unroll
    for (int i = 0; i < 4; i++) {
        const int r0 = bm + wm * 64 + i * 16 + grp;
        #pragma unroll
        for (int j = 0; j < 4; j++) {
            const int col = bn + wn * 32 + j * 8 + tig * 2;
            float2 bv = *(const float2*)(bias + col);
            float2 v0 = { acc[i][j][0] + bv.x, acc[i][j][1] + bv.y };
            float2 v1 = { acc[i][j][2] + bv.x, acc[i][j][3] + bv.y };
            if (STREAM) {
                __stcs((float2*)(C + (size_t)r0 * N + col), v0);
                __stcs((float2*)(C + (size_t)(r0 + 8) * N + col), v1);
            } else {
                *(float2*)(C + (size_t)r0 * N + col)       = v0;
                *(float2*)(C + (size_t)(r0 + 8) * N + col) = v1;
            }
        }
    }
    #undef ISSUE
    #undef AF_LOAD
    #undef BF_LOAD
    #undef MMA_SLICE
}

__global__ void __launch_bounds__(256, 2) qkv_gemm_kernel(
    const float* __restrict__ qb, const float* __restrict__ kb,
    const float* __restrict__ vb, int layer)
{
    const size_t lo = (size_t)layer * D_ * D_;
    const uint32_t* W; const float* bb; float* C;
    if (blockIdx.z == 0)      { W = g_wq + lo; bb = qb; C = g_q; }
    else if (blockIdx.z == 1) { W = g_wk + lo; bb = kb; C = g_k; }
    else                      { W = g_wv + lo; bb = vb; C = g_v; }
    gemm_body<false>(g_xr, W, bb, C, D_, blockIdx.x * 128, blockIdx.y * 128);
}

__global__ void __launch_bounds__(256, 2) out_gemm_kernel(
    const float* __restrict__ bias, float* __restrict__ C)
{
    gemm_body<true>(g_xr, g_wo, bias, C, V_, blockIdx.x * 128, blockIdx.y * 128);
}

// ---------------------------------------------------------------------------
// Attention: one block per (b, h). S=24, DH=64. Fused residual.
// ---------------------------------------------------------------------------
__global__ void __launch_bounds__(256) attn_kernel()
{
    __shared__ float qs[S_][DH_];
    __shared__ float ks_[S_][DH_];
    __shared__ float vs[S_][DH_];
    __shared__ float sc[S_][S_];

    const int bh  = blockIdx.x;
    const int b   = bh >> 4;
    const int h   = bh & 15;
    const int tid = threadIdx.x;

    for (int idx = tid; idx < S_ * DH_ / 4; idx += 256) {
        int s = idx >> 4, c4 = (idx & 15) * 4;
        size_t off = ((size_t)s * B_ + b) * D_ + h * DH_ + c4;
        *(float4*)&qs[s][c4]  = *(const float4*)(g_q + off);
        *(float4*)&ks_[s][c4] = *(const float4*)(g_k + off);
        *(float4*)&vs[s][c4]  = *(const float4*)(g_v + off);
    }
    __syncthreads();

    const float scale = 0.03125f;   // 1/sqrt(1024)
    for (int idx = tid; idx < S_ * S_; idx += 256) {
        int s = idx / S_, t = idx % S_;
        float dot = 0.f;
        #pragma unroll
        for (int d = 0; d < DH_; d++) dot = fmaf(qs[s][d], ks_[t][d], dot);
        sc[s][t] = dot * scale;
    }
    __syncthreads();

    if (tid < S_) {
        float m = -1e30f;
        #pragma unroll
        for (int t = 0; t < S_; t++) m = fmaxf(m, sc[tid][t]);
        float sum = 0.f;
        #pragma unroll
        for (int t = 0; t < S_; t++) {
            float e = expf(sc[tid][t] - m);
            sc[tid][t] = e;
            sum += e;
        }
        float inv = 1.f / sum;
        #pragma unroll
        for (int t = 0; t < S_; t++) sc[tid][t] *= inv;
    }
    __syncthreads();

    for (int idx = tid; idx < S_ * DH_ / 4; idx += 256) {
        int s = idx >> 4, c4 = (idx & 15) * 4;
        float4 o = {0.f, 0.f, 0.f, 0.f};
        #pragma unroll
        for (int t = 0; t < S_; t++) {
            float p = sc[s][t];
            float4 vv = *(const float4*)&vs[t][c4];
            o.x = fmaf(p, vv.x, o.x);
            o.y = fmaf(p, vv.y, o.y);
            o.z = fmaf(p, vv.z, o.z);
            o.w = fmaf(p, vv.w, o.w);
        }
        size_t off = ((size_t)s * B_ + b) * D_ + h * DH_ + c4;
        float4 xv = *(const float4*)(g_x + off);
        xv.x += o.x; xv.y += o.y; xv.z += o.z; xv.w += o.w;
        *(float4*)(g_x + off) = xv;
        uint4 r = { f2tf(xv.x), f2tf(xv.y), f2tf(xv.z), f2tf(xv.w) };
        *(uint4*)(g_xr + off) = r;
    }
}

// ---------------------------------------------------------------------------
// Launch
// ---------------------------------------------------------------------------
extern "C" void kernel_launch(void* const* d_in, const int* in_sizes, int n_in,
                              void* d_out, int out_size)
{
    const int*   inp = (const int*)  d_in[0];
    const float* tok = (const float*)d_in[2];
    const float* pe  = (const float*)d_in[3];
    const float* qw  = (const float*)d_in[4];
    const float* qb  = (const float*)d_in[5];
    const float* kw  = (const float*)d_in[6];
    const float* kb  = (const float*)d_in[7];
    const float* vw  = (const float*)d_in[8];
    const float* vb  = (const float*)d_in[9];
    const float* ow  = (const float*)d_in[10];
    const float* ob  = (const float*)d_in[11];
    float* out = (float*)d_out;

    cudaFuncSetAttribute(qkv_gemm_kernel, cudaFuncAttributeMaxDynamicSharedMemorySize, SMEM_BYTES);
    cudaFuncSetAttribute(out_gemm_kernel, cudaFuncAttributeMaxDynamicSharedMemorySize, SMEM_BYTES);

    embed_kernel<<<NTOK * D_ / 4 / 256, 256>>>(inp, tok, pe);
    conv_all_kernel<<<dim3(D_ * D_ / 4 / 256, L_, 3), 256>>>(qw, kw, vw);
    conv_out_kernel<<<(size_t)V_ * D_ / 4 / 256, 256>>>(ow);

    for (int l = 0; l < L_; l++) {
        const size_t bo = (size_t)l * D_;
        qkv_gemm_kernel<<<dim3(NTOK / 128, D_ / 128, 3), 256, SMEM_BYTES>>>(
            qb + bo, kb + bo, vb + bo, l);
        attn_kernel<<<B_ * H_, 256>>>();
    }

    out_gemm_kernel<<<dim3(NTOK / 128, V_ / 128), 256, SMEM_BYTES>>>(ob, out);
}